// round 1
// baseline (speedup 1.0000x reference)
#include <cuda_runtime.h>
#include <math.h>

// Problem constants (B=2, T=2048, C=1024, 16 heads, head_dim=64)
#define Bb 2
#define Tt 2048
#define Cc 1024
#define Hh 16
#define Dd 64
#define Mm (Bb * Tt)   // 4096 rows

// Scratch (device globals; no allocation allowed)
__device__ float g_Q[Bb * Tt * Cc];
__device__ float g_K[Bb * Tt * Cc];
__device__ float g_V[Bb * Tt * Cc];
__device__ float g_Y[Bb * Tt * Cc];

// ---------------------------------------------------------------------------
// GEMM: Out[m][n] = sum_k A[m][k] * W[n][k]   (y = x @ W^T, W stored [out,in])
// 128x128x8 tile, 256 threads, 8x8 microtile.
// ---------------------------------------------------------------------------
#define GBM 128
#define GBN 128
#define GBK 8

__global__ __launch_bounds__(256) void gemm_nt_kernel(
    const float* __restrict__ A, const float* __restrict__ W,
    float* __restrict__ Out, int M, int N, int K)
{
    __shared__ float As[GBK][GBM];
    __shared__ float Bs[GBK][GBN];

    const int tid = threadIdx.x;
    const int tx = tid & 15;        // 0..15 -> n microtile
    const int ty = tid >> 4;        // 0..15 -> m microtile
    const int m0 = blockIdx.y * GBM;
    const int n0 = blockIdx.x * GBN;

    const int lrow = tid >> 1;          // 0..127
    const int lc4  = (tid & 1) * 4;     // 0 or 4

    const float* Aptr = A + (size_t)(m0 + lrow) * K + lc4;
    const float* Wptr = W + (size_t)(n0 + lrow) * K + lc4;

    float acc[8][8];
#pragma unroll
    for (int i = 0; i < 8; i++)
#pragma unroll
        for (int j = 0; j < 8; j++) acc[i][j] = 0.f;

    for (int k0 = 0; k0 < K; k0 += GBK) {
        float4 a = *(const float4*)(Aptr + k0);
        float4 w = *(const float4*)(Wptr + k0);
        __syncthreads();
        As[lc4 + 0][lrow] = a.x; As[lc4 + 1][lrow] = a.y;
        As[lc4 + 2][lrow] = a.z; As[lc4 + 3][lrow] = a.w;
        Bs[lc4 + 0][lrow] = w.x; Bs[lc4 + 1][lrow] = w.y;
        Bs[lc4 + 2][lrow] = w.z; Bs[lc4 + 3][lrow] = w.w;
        __syncthreads();

#pragma unroll
        for (int kk = 0; kk < GBK; kk++) {
            float ar[8], br[8];
            *(float4*)&ar[0] = *(const float4*)&As[kk][ty * 8];
            *(float4*)&ar[4] = *(const float4*)&As[kk][ty * 8 + 4];
            *(float4*)&br[0] = *(const float4*)&Bs[kk][tx * 8];
            *(float4*)&br[4] = *(const float4*)&Bs[kk][tx * 8 + 4];
#pragma unroll
            for (int i = 0; i < 8; i++)
#pragma unroll
                for (int j = 0; j < 8; j++)
                    acc[i][j] += ar[i] * br[j];
        }
    }

#pragma unroll
    for (int i = 0; i < 8; i++) {
        float* orow = Out + (size_t)(m0 + ty * 8 + i) * N + n0 + tx * 8;
        float4 o0 = make_float4(acc[i][0], acc[i][1], acc[i][2], acc[i][3]);
        float4 o1 = make_float4(acc[i][4], acc[i][5], acc[i][6], acc[i][7]);
        *(float4*)(orow) = o0;
        *(float4*)(orow + 4) = o1;
    }
}

// ---------------------------------------------------------------------------
// RoPE applied in-place to Q and K. One block per (b,t) token, 512 threads:
// thread -> (head h = tid/32, pair i = tid%32). Matches jax fp32 math.
// ---------------------------------------------------------------------------
__global__ __launch_bounds__(512) void rope_kernel(float* __restrict__ Q,
                                                   float* __restrict__ K)
{
    const int bt = blockIdx.x;
    const int t = bt & (Tt - 1);
    const int h = threadIdx.x >> 5;
    const int i = threadIdx.x & 31;

    const float inv = powf(10000.0f, -(float)(2 * i) / 64.0f);
    const float ang = (float)t * inv;
    const float c = cosf(ang);
    const float s = sinf(ang);

    const size_t base = (size_t)bt * Cc + h * Dd;

    float q1 = Q[base + i], q2 = Q[base + i + 32];
    Q[base + i]      = q1 * c - q2 * s;
    Q[base + i + 32] = q2 * c + q1 * s;

    float k1 = K[base + i], k2 = K[base + i + 32];
    K[base + i]      = k1 * c - k2 * s;
    K[base + i + 32] = k2 * c + k1 * s;
}

// ---------------------------------------------------------------------------
// Flash attention (causal), per-(b,h,q-tile of 64). 256 threads:
// 4 lanes per q-row; each lane owns 16 S columns and 16 O columns.
// Online softmax with shfl reductions within the 4-lane row group.
// ---------------------------------------------------------------------------
__global__ __launch_bounds__(256) void attn_kernel(
    const float* __restrict__ Qg, const float* __restrict__ Kg,
    const float* __restrict__ Vg, float* __restrict__ Yg)
{
    __shared__ float Qs[64][68];     // padded stride 68 (float4 aligned, bank-safe)
    __shared__ float KVs[64 * 64];   // K or V tile, row-major 64 floats/row

    const int qt = blockIdx.x;
    const int h  = blockIdx.y;
    const int b  = blockIdx.z;
    const int tid = threadIdx.x;
    const int r    = tid >> 2;   // q-row within tile
    const int quad = tid & 3;    // column quarter
    const int tq = qt * 64 + r;

    const float scale = 0.125f;  // 1/sqrt(64)

    // Load scaled Q tile
    {
        const float* src = Qg + ((size_t)(b * Tt + qt * 64)) * Cc + h * Dd;
        for (int idx = tid; idx < 64 * 16; idx += 256) {
            int row = idx >> 4, c4 = idx & 15;
            float4 v = *(const float4*)(src + (size_t)row * Cc + c4 * 4);
            v.x *= scale; v.y *= scale; v.z *= scale; v.w *= scale;
            *(float4*)&Qs[row][c4 * 4] = v;
        }
    }

    float O[16];
#pragma unroll
    for (int d = 0; d < 16; d++) O[d] = 0.f;
    float m_run = -1e30f;
    float l_run = 0.f;

    float4* KV4 = (float4*)KVs;

    for (int kt = 0; kt <= qt; kt++) {
        // ---- load K tile ----
        __syncthreads();
        {
            const float* src = Kg + ((size_t)(b * Tt + kt * 64)) * Cc + h * Dd;
            for (int idx = tid; idx < 1024; idx += 256) {
                int row = idx >> 4, c4 = idx & 15;
                KV4[idx] = *(const float4*)(src + (size_t)row * Cc + c4 * 4);
            }
        }
        __syncthreads();

        // ---- S = Q K^T (this lane's 16 columns) ----
        float s[16];
#pragma unroll
        for (int jj = 0; jj < 16; jj++) s[jj] = 0.f;
        const float4* Qrow = (const float4*)&Qs[r][0];
        for (int kk4 = 0; kk4 < 16; kk4++) {
            float4 q = Qrow[kk4];
#pragma unroll
            for (int jj = 0; jj < 16; jj++) {
                float4 kv = KV4[(quad * 16 + jj) * 16 + kk4];
                s[jj] += q.x * kv.x + q.y * kv.y + q.z * kv.z + q.w * kv.w;
            }
        }

        // ---- causal mask on diagonal tile ----
        if (kt == qt) {
#pragma unroll
            for (int jj = 0; jj < 16; jj++)
                if (quad * 16 + jj > r) s[jj] = -1e30f;
        }

        // ---- online softmax (row reduction across the 4-lane group) ----
        float mloc = m_run;
#pragma unroll
        for (int jj = 0; jj < 16; jj++) mloc = fmaxf(mloc, s[jj]);
        mloc = fmaxf(mloc, __shfl_xor_sync(0xffffffffu, mloc, 1));
        mloc = fmaxf(mloc, __shfl_xor_sync(0xffffffffu, mloc, 2));

        float alpha = expf(m_run - mloc);
        float lsum = 0.f;
#pragma unroll
        for (int jj = 0; jj < 16; jj++) {
            s[jj] = expf(s[jj] - mloc);
            lsum += s[jj];
        }
        lsum += __shfl_xor_sync(0xffffffffu, lsum, 1);
        lsum += __shfl_xor_sync(0xffffffffu, lsum, 2);
        l_run = l_run * alpha + lsum;
        m_run = mloc;
#pragma unroll
        for (int d = 0; d < 16; d++) O[d] *= alpha;

        // ---- load V tile (overwrite KVs) ----
        __syncthreads();
        {
            const float* src = Vg + ((size_t)(b * Tt + kt * 64)) * Cc + h * Dd;
            for (int idx = tid; idx < 1024; idx += 256) {
                int row = idx >> 4, c4 = idx & 15;
                KV4[idx] = *(const float4*)(src + (size_t)row * Cc + c4 * 4);
            }
        }
        __syncthreads();

        // ---- O += P V : gather p from the 4-lane group via shfl ----
        for (int jq = 0; jq < 4; jq++) {
#pragma unroll
            for (int jj = 0; jj < 16; jj++) {
                float p = __shfl_sync(0xffffffffu, s[jj], jq, 4);
                int j = jq * 16 + jj;
                const float4* Vr = &KV4[j * 16 + quad * 4];
                float4 v0 = Vr[0], v1 = Vr[1], v2 = Vr[2], v3 = Vr[3];
                O[0]  += p * v0.x; O[1]  += p * v0.y; O[2]  += p * v0.z; O[3]  += p * v0.w;
                O[4]  += p * v1.x; O[5]  += p * v1.y; O[6]  += p * v1.z; O[7]  += p * v1.w;
                O[8]  += p * v2.x; O[9]  += p * v2.y; O[10] += p * v2.z; O[11] += p * v2.w;
                O[12] += p * v3.x; O[13] += p * v3.y; O[14] += p * v3.z; O[15] += p * v3.w;
            }
        }
    }

    // ---- write normalized output ----
    float inv = 1.f / l_run;
    float* dst = Yg + ((size_t)(b * Tt + tq)) * Cc + h * Dd + quad * 16;
#pragma unroll
    for (int d4 = 0; d4 < 4; d4++) {
        float4 o = make_float4(O[d4 * 4 + 0] * inv, O[d4 * 4 + 1] * inv,
                               O[d4 * 4 + 2] * inv, O[d4 * 4 + 3] * inv);
        *(float4*)(dst + d4 * 4) = o;
    }
}

// ---------------------------------------------------------------------------
// Launch
// ---------------------------------------------------------------------------
extern "C" void kernel_launch(void* const* d_in, const int* in_sizes, int n_in,
                              void* d_out, int out_size)
{
    const float* x  = (const float*)d_in[0];
    const float* Wq = (const float*)d_in[1];
    const float* Wk = (const float*)d_in[2];
    const float* Wv = (const float*)d_in[3];
    const float* Wo = (const float*)d_in[4];
    float* out = (float*)d_out;

    float *qp, *kp, *vp, *yp;
    cudaGetSymbolAddress((void**)&qp, g_Q);
    cudaGetSymbolAddress((void**)&kp, g_K);
    cudaGetSymbolAddress((void**)&vp, g_V);
    cudaGetSymbolAddress((void**)&yp, g_Y);

    dim3 ggrid(Cc / GBN, Mm / GBM);   // (8, 32)
    gemm_nt_kernel<<<ggrid, 256>>>(x, Wq, qp, Mm, Cc, Cc);
    gemm_nt_kernel<<<ggrid, 256>>>(x, Wk, kp, Mm, Cc, Cc);
    gemm_nt_kernel<<<ggrid, 256>>>(x, Wv, vp, Mm, Cc, Cc);

    rope_kernel<<<Bb * Tt, 512>>>(qp, kp);

    dim3 agrid(Tt / 64, Hh, Bb);      // (32, 16, 2)
    attn_kernel<<<agrid, 256>>>(qp, kp, vp, yp);

    gemm_nt_kernel<<<ggrid, 256>>>(yp, Wo, out, Mm, Cc, Cc);
}

// round 6
// speedup vs baseline: 1.0813x; 1.0813x over previous
#include <cuda_runtime.h>
#include <math.h>
#include <stdint.h>

// Problem constants (B=2, T=2048, C=1024, 16 heads, head_dim=64)
#define Bb 2
#define Tt 2048
#define Cc 1024
#define Hh 16
#define Dd 64
#define Mm (Bb * Tt)   // 4096 rows

// Scratch (device globals; no allocation allowed)
__device__ float g_Q[Bb * Tt * Cc];
__device__ float g_K[Bb * Tt * Cc];
__device__ float g_V[Bb * Tt * Cc];
__device__ float g_Y[Bb * Tt * Cc];

// ---------------------------------------------------------------------------
// Tensor-core GEMM (3xTF32): Out[m][n] = sum_k A[m][k] * W[n][k]
// 128x128 tile, K-step 16, 256 threads (8 warps as 2x4), warp tile 64x32.
// mma.sync.aligned.m16n8k8.row.col.f32.tf32.tf32.f32
// A split into hi+lo tf32; error of dropped lo*lo term ~2^-22 (fp32-grade).
// ---------------------------------------------------------------------------
#define KB 16
#define SK 20   // smem row stride (floats): (20*m + k) % 32 distinct per 8-lane group

__device__ __forceinline__ uint32_t f2tf32(float v) {
    uint32_t r;
    asm("cvt.rna.tf32.f32 %0, %1;" : "=r"(r) : "f"(v));
    return r;
}

__device__ __forceinline__ void mma_tf32(float4& c, uint32_t a0, uint32_t a1,
                                         uint32_t a2, uint32_t a3,
                                         uint32_t b0, uint32_t b1) {
    asm volatile(
        "mma.sync.aligned.m16n8k8.row.col.f32.tf32.tf32.f32 "
        "{%0,%1,%2,%3}, {%4,%5,%6,%7}, {%8,%9}, {%0,%1,%2,%3};"
        : "+f"(c.x), "+f"(c.y), "+f"(c.z), "+f"(c.w)
        : "r"(a0), "r"(a1), "r"(a2), "r"(a3), "r"(b0), "r"(b1));
}

__global__ __launch_bounds__(256, 2) void gemm_tc_kernel(
    const float* __restrict__ A, const float* __restrict__ W,
    float* __restrict__ Out, int M, int N, int K)
{
    __shared__ float Ah[128][SK];
    __shared__ float Al[128][SK];
    __shared__ float Bh[128][SK];
    __shared__ float Bl[128][SK];

    const int tid  = threadIdx.x;
    const int lane = tid & 31;
    const int wid  = tid >> 5;
    const int warp_m = wid >> 2;           // 0..1 -> m offset *64
    const int warp_n = wid & 3;            // 0..3 -> n offset *32
    const int m0 = blockIdx.y * 128;
    const int n0 = blockIdx.x * 128;

    const int lr = tid >> 2;               // 0..63 (row for gmem loads)
    const int lc = (tid & 3) * 4;          // col quad

    const float* Ap0 = A + (size_t)(m0 + lr) * K + lc;
    const float* Ap1 = A + (size_t)(m0 + lr + 64) * K + lc;
    const float* Wp0 = W + (size_t)(n0 + lr) * K + lc;
    const float* Wp1 = W + (size_t)(n0 + lr + 64) * K + lc;

    float4 acc[4][4];
#pragma unroll
    for (int i = 0; i < 4; i++)
#pragma unroll
        for (int j = 0; j < 4; j++) acc[i][j] = make_float4(0.f, 0.f, 0.f, 0.f);

    const int lg = lane >> 2;   // group 0..7
    const int lk = lane & 3;    // k-sub 0..3

    for (int k0 = 0; k0 < K; k0 += KB) {
        float4 a0 = *(const float4*)(Ap0 + k0);
        float4 a1 = *(const float4*)(Ap1 + k0);
        float4 w0 = *(const float4*)(Wp0 + k0);
        float4 w1 = *(const float4*)(Wp1 + k0);
        __syncthreads();
        {
            const float* va[4] = {(const float*)&a0, (const float*)&a1,
                                  (const float*)&w0, (const float*)&w1};
            float* dh[4] = {&Ah[lr][lc], &Ah[lr + 64][lc], &Bh[lr][lc], &Bh[lr + 64][lc]};
            float* dl[4] = {&Al[lr][lc], &Al[lr + 64][lc], &Bl[lr][lc], &Bl[lr + 64][lc]};
#pragma unroll
            for (int q = 0; q < 4; q++) {
                float4 hi4, lo4;
                float* h = (float*)&hi4;
                float* l = (float*)&lo4;
#pragma unroll
                for (int j = 0; j < 4; j++) {
                    float v = va[q][j];
                    uint32_t hb = f2tf32(v);
                    float hf = __uint_as_float(hb);
                    uint32_t lb = f2tf32(v - hf);
                    h[j] = hf;
                    l[j] = __uint_as_float(lb);
                }
                *(float4*)dh[q] = hi4;
                *(float4*)dl[q] = lo4;
            }
        }
        __syncthreads();

#pragma unroll
        for (int kb = 0; kb < KB; kb += 8) {
            // A fragments for 4 m-tiles (hi and lo)
            uint32_t ah[4][4], al[4][4];
#pragma unroll
            for (int mi = 0; mi < 4; mi++) {
                int r0 = warp_m * 64 + mi * 16 + lg;
                ah[mi][0] = __float_as_uint(Ah[r0][kb + lk]);
                ah[mi][1] = __float_as_uint(Ah[r0 + 8][kb + lk]);
                ah[mi][2] = __float_as_uint(Ah[r0][kb + 4 + lk]);
                ah[mi][3] = __float_as_uint(Ah[r0 + 8][kb + 4 + lk]);
                al[mi][0] = __float_as_uint(Al[r0][kb + lk]);
                al[mi][1] = __float_as_uint(Al[r0 + 8][kb + lk]);
                al[mi][2] = __float_as_uint(Al[r0][kb + 4 + lk]);
                al[mi][3] = __float_as_uint(Al[r0 + 8][kb + 4 + lk]);
            }
#pragma unroll
            for (int ni = 0; ni < 4; ni++) {
                int nrow = warp_n * 32 + ni * 8 + lg;
                uint32_t bh0 = __float_as_uint(Bh[nrow][kb + lk]);
                uint32_t bh1 = __float_as_uint(Bh[nrow][kb + 4 + lk]);
                uint32_t bl0 = __float_as_uint(Bl[nrow][kb + lk]);
                uint32_t bl1 = __float_as_uint(Bl[nrow][kb + 4 + lk]);
#pragma unroll
                for (int mi = 0; mi < 4; mi++) {
                    mma_tf32(acc[mi][ni], ah[mi][0], ah[mi][1], ah[mi][2], ah[mi][3], bh0, bh1);
                    mma_tf32(acc[mi][ni], al[mi][0], al[mi][1], al[mi][2], al[mi][3], bh0, bh1);
                    mma_tf32(acc[mi][ni], ah[mi][0], ah[mi][1], ah[mi][2], ah[mi][3], bl0, bl1);
                }
            }
        }
    }

    // Epilogue
#pragma unroll
    for (int mi = 0; mi < 4; mi++) {
        int r0 = m0 + warp_m * 64 + mi * 16 + lg;
#pragma unroll
        for (int ni = 0; ni < 4; ni++) {
            int c0 = n0 + warp_n * 32 + ni * 8 + 2 * lk;
            float4 c = acc[mi][ni];
            *(float2*)(Out + (size_t)r0 * N + c0) = make_float2(c.x, c.y);
            *(float2*)(Out + (size_t)(r0 + 8) * N + c0) = make_float2(c.z, c.w);
        }
    }
}

// ---------------------------------------------------------------------------
// RoPE applied in-place to Q and K (unchanged).
// ---------------------------------------------------------------------------
__global__ __launch_bounds__(512) void rope_kernel(float* __restrict__ Q,
                                                   float* __restrict__ K)
{
    const int bt = blockIdx.x;
    const int t = bt & (Tt - 1);
    const int h = threadIdx.x >> 5;
    const int i = threadIdx.x & 31;

    const float inv = powf(10000.0f, -(float)(2 * i) / 64.0f);
    const float ang = (float)t * inv;
    const float c = cosf(ang);
    const float s = sinf(ang);

    const size_t base = (size_t)bt * Cc + h * Dd;

    float q1 = Q[base + i], q2 = Q[base + i + 32];
    Q[base + i]      = q1 * c - q2 * s;
    Q[base + i + 32] = q2 * c + q1 * s;

    float k1 = K[base + i], k2 = K[base + i + 32];
    K[base + i]      = k1 * c - k2 * s;
    K[base + i + 32] = k2 * c + k1 * s;
}

// ---------------------------------------------------------------------------
// Flash attention (causal) — unchanged from R1.
// ---------------------------------------------------------------------------
__global__ __launch_bounds__(256) void attn_kernel(
    const float* __restrict__ Qg, const float* __restrict__ Kg,
    const float* __restrict__ Vg, float* __restrict__ Yg)
{
    __shared__ float Qs[64][68];
    __shared__ float KVs[64 * 64];

    const int qt = blockIdx.x;
    const int h  = blockIdx.y;
    const int b  = blockIdx.z;
    const int tid = threadIdx.x;
    const int r    = tid >> 2;
    const int quad = tid & 3;
    const int tq = qt * 64 + r;

    const float scale = 0.125f;

    {
        const float* src = Qg + ((size_t)(b * Tt + qt * 64)) * Cc + h * Dd;
        for (int idx = tid; idx < 64 * 16; idx += 256) {
            int row = idx >> 4, c4 = idx & 15;
            float4 v = *(const float4*)(src + (size_t)row * Cc + c4 * 4);
            v.x *= scale; v.y *= scale; v.z *= scale; v.w *= scale;
            *(float4*)&Qs[row][c4 * 4] = v;
        }
    }

    float O[16];
#pragma unroll
    for (int d = 0; d < 16; d++) O[d] = 0.f;
    float m_run = -1e30f;
    float l_run = 0.f;

    float4* KV4 = (float4*)KVs;

    for (int kt = 0; kt <= qt; kt++) {
        __syncthreads();
        {
            const float* src = Kg + ((size_t)(b * Tt + kt * 64)) * Cc + h * Dd;
            for (int idx = tid; idx < 1024; idx += 256) {
                int row = idx >> 4, c4 = idx & 15;
                KV4[idx] = *(const float4*)(src + (size_t)row * Cc + c4 * 4);
            }
        }
        __syncthreads();

        float s[16];
#pragma unroll
        for (int jj = 0; jj < 16; jj++) s[jj] = 0.f;
        const float4* Qrow = (const float4*)&Qs[r][0];
        for (int kk4 = 0; kk4 < 16; kk4++) {
            float4 q = Qrow[kk4];
#pragma unroll
            for (int jj = 0; jj < 16; jj++) {
                float4 kv = KV4[(quad * 16 + jj) * 16 + kk4];
                s[jj] += q.x * kv.x + q.y * kv.y + q.z * kv.z + q.w * kv.w;
            }
        }

        if (kt == qt) {
#pragma unroll
            for (int jj = 0; jj < 16; jj++)
                if (quad * 16 + jj > r) s[jj] = -1e30f;
        }

        float mloc = m_run;
#pragma unroll
        for (int jj = 0; jj < 16; jj++) mloc = fmaxf(mloc, s[jj]);
        mloc = fmaxf(mloc, __shfl_xor_sync(0xffffffffu, mloc, 1));
        mloc = fmaxf(mloc, __shfl_xor_sync(0xffffffffu, mloc, 2));

        float alpha = expf(m_run - mloc);
        float lsum = 0.f;
#pragma unroll
        for (int jj = 0; jj < 16; jj++) {
            s[jj] = expf(s[jj] - mloc);
            lsum += s[jj];
        }
        lsum += __shfl_xor_sync(0xffffffffu, lsum, 1);
        lsum += __shfl_xor_sync(0xffffffffu, lsum, 2);
        l_run = l_run * alpha + lsum;
        m_run = mloc;
#pragma unroll
        for (int d = 0; d < 16; d++) O[d] *= alpha;

        __syncthreads();
        {
            const float* src = Vg + ((size_t)(b * Tt + kt * 64)) * Cc + h * Dd;
            for (int idx = tid; idx < 1024; idx += 256) {
                int row = idx >> 4, c4 = idx & 15;
                KV4[idx] = *(const float4*)(src + (size_t)row * Cc + c4 * 4);
            }
        }
        __syncthreads();

        for (int jq = 0; jq < 4; jq++) {
#pragma unroll
            for (int jj = 0; jj < 16; jj++) {
                float p = __shfl_sync(0xffffffffu, s[jj], jq, 4);
                int j = jq * 16 + jj;
                const float4* Vr = &KV4[j * 16 + quad * 4];
                float4 v0 = Vr[0], v1 = Vr[1], v2 = Vr[2], v3 = Vr[3];
                O[0]  += p * v0.x; O[1]  += p * v0.y; O[2]  += p * v0.z; O[3]  += p * v0.w;
                O[4]  += p * v1.x; O[5]  += p * v1.y; O[6]  += p * v1.z; O[7]  += p * v1.w;
                O[8]  += p * v2.x; O[9]  += p * v2.y; O[10] += p * v2.z; O[11] += p * v2.w;
                O[12] += p * v3.x; O[13] += p * v3.y; O[14] += p * v3.z; O[15] += p * v3.w;
            }
        }
    }

    float inv = 1.f / l_run;
    float* dst = Yg + ((size_t)(b * Tt + tq)) * Cc + h * Dd + quad * 16;
#pragma unroll
    for (int d4 = 0; d4 < 4; d4++) {
        float4 o = make_float4(O[d4 * 4 + 0] * inv, O[d4 * 4 + 1] * inv,
                               O[d4 * 4 + 2] * inv, O[d4 * 4 + 3] * inv);
        *(float4*)(dst + d4 * 4) = o;
    }
}

// ---------------------------------------------------------------------------
// Launch
// ---------------------------------------------------------------------------
extern "C" void kernel_launch(void* const* d_in, const int* in_sizes, int n_in,
                              void* d_out, int out_size)
{
    const float* x  = (const float*)d_in[0];
    const float* Wq = (const float*)d_in[1];
    const float* Wk = (const float*)d_in[2];
    const float* Wv = (const float*)d_in[3];
    const float* Wo = (const float*)d_in[4];
    float* out = (float*)d_out;

    float *qp, *kp, *vp, *yp;
    cudaGetSymbolAddress((void**)&qp, g_Q);
    cudaGetSymbolAddress((void**)&kp, g_K);
    cudaGetSymbolAddress((void**)&vp, g_V);
    cudaGetSymbolAddress((void**)&yp, g_Y);

    dim3 ggrid(Cc / 128, Mm / 128);   // (8, 32)
    gemm_tc_kernel<<<ggrid, 256>>>(x, Wq, qp, Mm, Cc, Cc);
    gemm_tc_kernel<<<ggrid, 256>>>(x, Wk, kp, Mm, Cc, Cc);
    gemm_tc_kernel<<<ggrid, 256>>>(x, Wv, vp, Mm, Cc, Cc);

    rope_kernel<<<Bb * Tt, 512>>>(qp, kp);

    dim3 agrid(Tt / 64, Hh, Bb);      // (32, 16, 2)
    attn_kernel<<<agrid, 256>>>(qp, kp, vp, yp);

    gemm_tc_kernel<<<ggrid, 256>>>(yp, Wo, out, Mm, Cc, Cc);
}

// round 8
// speedup vs baseline: 4.2345x; 3.9162x over previous
#include <cuda_runtime.h>
#include <math.h>
#include <stdint.h>

// Problem constants (B=2, T=2048, C=1024, 16 heads, head_dim=64)
#define Bb 2
#define Tt 2048
#define Cc 1024
#define Hh 16
#define Dd 64
#define Mm (Bb * Tt)   // 4096 rows

// Scratch (device globals; no allocation allowed)
__device__ float g_Q[Bb * Tt * Cc];
__device__ float g_K[Bb * Tt * Cc];
__device__ float g_V[Bb * Tt * Cc];
__device__ float g_Y[Bb * Tt * Cc];

// ---------------------------------------------------------------------------
// Common TF32 helpers
// ---------------------------------------------------------------------------
__device__ __forceinline__ uint32_t f2tf32(float v) {
    uint32_t r;
    asm("cvt.rna.tf32.f32 %0, %1;" : "=r"(r) : "f"(v));
    return r;
}

__device__ __forceinline__ void split_tf32(float v, float& hi, float& lo) {
    uint32_t hb = f2tf32(v);
    float hf = __uint_as_float(hb);
    hi = hf;
    lo = __uint_as_float(f2tf32(v - hf));
}

__device__ __forceinline__ void mma_tf32(float4& c, uint32_t a0, uint32_t a1,
                                         uint32_t a2, uint32_t a3,
                                         uint32_t b0, uint32_t b1) {
    asm("mma.sync.aligned.m16n8k8.row.col.f32.tf32.tf32.f32 "
        "{%0,%1,%2,%3}, {%4,%5,%6,%7}, {%8,%9}, {%0,%1,%2,%3};"
        : "+f"(c.x), "+f"(c.y), "+f"(c.z), "+f"(c.w)
        : "r"(a0), "r"(a1), "r"(a2), "r"(a3), "r"(b0), "r"(b1));
}

// ---------------------------------------------------------------------------
// Tensor-core GEMM (3xTF32): Out[m][n] = sum_k A[m][k] * W[n][k]
// (unchanged from R6 — verified correct)
// ---------------------------------------------------------------------------
#define KB 16
#define SK 20

__global__ __launch_bounds__(256, 2) void gemm_tc_kernel(
    const float* __restrict__ A, const float* __restrict__ W,
    float* __restrict__ Out, int M, int N, int K)
{
    __shared__ float Ah[128][SK];
    __shared__ float Al[128][SK];
    __shared__ float Bh[128][SK];
    __shared__ float Bl[128][SK];

    const int tid  = threadIdx.x;
    const int lane = tid & 31;
    const int wid  = tid >> 5;
    const int warp_m = wid >> 2;
    const int warp_n = wid & 3;
    const int m0 = blockIdx.y * 128;
    const int n0 = blockIdx.x * 128;

    const int lr = tid >> 2;
    const int lc = (tid & 3) * 4;

    const float* Ap0 = A + (size_t)(m0 + lr) * K + lc;
    const float* Ap1 = A + (size_t)(m0 + lr + 64) * K + lc;
    const float* Wp0 = W + (size_t)(n0 + lr) * K + lc;
    const float* Wp1 = W + (size_t)(n0 + lr + 64) * K + lc;

    float4 acc[4][4];
#pragma unroll
    for (int i = 0; i < 4; i++)
#pragma unroll
        for (int j = 0; j < 4; j++) acc[i][j] = make_float4(0.f, 0.f, 0.f, 0.f);

    const int lg = lane >> 2;
    const int lk = lane & 3;

    for (int k0 = 0; k0 < K; k0 += KB) {
        float4 a0 = *(const float4*)(Ap0 + k0);
        float4 a1 = *(const float4*)(Ap1 + k0);
        float4 w0 = *(const float4*)(Wp0 + k0);
        float4 w1 = *(const float4*)(Wp1 + k0);
        __syncthreads();
        {
            const float* va[4] = {(const float*)&a0, (const float*)&a1,
                                  (const float*)&w0, (const float*)&w1};
            float* dh[4] = {&Ah[lr][lc], &Ah[lr + 64][lc], &Bh[lr][lc], &Bh[lr + 64][lc]};
            float* dl[4] = {&Al[lr][lc], &Al[lr + 64][lc], &Bl[lr][lc], &Bl[lr + 64][lc]};
#pragma unroll
            for (int q = 0; q < 4; q++) {
                float4 hi4, lo4;
                float* h = (float*)&hi4;
                float* l = (float*)&lo4;
#pragma unroll
                for (int j = 0; j < 4; j++)
                    split_tf32(va[q][j], h[j], l[j]);
                *(float4*)dh[q] = hi4;
                *(float4*)dl[q] = lo4;
            }
        }
        __syncthreads();

#pragma unroll
        for (int kb = 0; kb < KB; kb += 8) {
            uint32_t ah[4][4], al[4][4];
#pragma unroll
            for (int mi = 0; mi < 4; mi++) {
                int r0 = warp_m * 64 + mi * 16 + lg;
                ah[mi][0] = __float_as_uint(Ah[r0][kb + lk]);
                ah[mi][1] = __float_as_uint(Ah[r0 + 8][kb + lk]);
                ah[mi][2] = __float_as_uint(Ah[r0][kb + 4 + lk]);
                ah[mi][3] = __float_as_uint(Ah[r0 + 8][kb + 4 + lk]);
                al[mi][0] = __float_as_uint(Al[r0][kb + lk]);
                al[mi][1] = __float_as_uint(Al[r0 + 8][kb + lk]);
                al[mi][2] = __float_as_uint(Al[r0][kb + 4 + lk]);
                al[mi][3] = __float_as_uint(Al[r0 + 8][kb + 4 + lk]);
            }
#pragma unroll
            for (int ni = 0; ni < 4; ni++) {
                int nrow = warp_n * 32 + ni * 8 + lg;
                uint32_t bh0 = __float_as_uint(Bh[nrow][kb + lk]);
                uint32_t bh1 = __float_as_uint(Bh[nrow][kb + 4 + lk]);
                uint32_t bl0 = __float_as_uint(Bl[nrow][kb + lk]);
                uint32_t bl1 = __float_as_uint(Bl[nrow][kb + 4 + lk]);
#pragma unroll
                for (int mi = 0; mi < 4; mi++) {
                    mma_tf32(acc[mi][ni], ah[mi][0], ah[mi][1], ah[mi][2], ah[mi][3], bh0, bh1);
                    mma_tf32(acc[mi][ni], al[mi][0], al[mi][1], al[mi][2], al[mi][3], bh0, bh1);
                    mma_tf32(acc[mi][ni], ah[mi][0], ah[mi][1], ah[mi][2], ah[mi][3], bl0, bl1);
                }
            }
        }
    }

#pragma unroll
    for (int mi = 0; mi < 4; mi++) {
        int r0 = m0 + warp_m * 64 + mi * 16 + lg;
#pragma unroll
        for (int ni = 0; ni < 4; ni++) {
            int c0 = n0 + warp_n * 32 + ni * 8 + 2 * lk;
            float4 c = acc[mi][ni];
            *(float2*)(Out + (size_t)r0 * N + c0) = make_float2(c.x, c.y);
            *(float2*)(Out + (size_t)(r0 + 8) * N + c0) = make_float2(c.z, c.w);
        }
    }
}

// ---------------------------------------------------------------------------
// RoPE applied in-place to Q and K (unchanged).
// ---------------------------------------------------------------------------
__global__ __launch_bounds__(512) void rope_kernel(float* __restrict__ Q,
                                                   float* __restrict__ K)
{
    const int bt = blockIdx.x;
    const int t = bt & (Tt - 1);
    const int h = threadIdx.x >> 5;
    const int i = threadIdx.x & 31;

    const float inv = powf(10000.0f, -(float)(2 * i) / 64.0f);
    const float ang = (float)t * inv;
    const float c = cosf(ang);
    const float s = sinf(ang);

    const size_t base = (size_t)bt * Cc + h * Dd;

    float q1 = Q[base + i], q2 = Q[base + i + 32];
    Q[base + i]      = q1 * c - q2 * s;
    Q[base + i + 32] = q2 * c + q1 * s;

    float k1 = K[base + i], k2 = K[base + i + 32];
    K[base + i]      = k1 * c - k2 * s;
    K[base + i + 32] = k2 * c + k1 * s;
}

// ---------------------------------------------------------------------------
// Tensor-core flash attention (causal), 3xTF32 for QK^T and P*V.
// Block: 128 threads (4 warps); Q tile 64 rows, 16 per warp. K/V tiles 64.
// Dynamic smem: bufH/bufL [64][68] (K hi/lo, then V^T hi/lo), per-warp P strip.
// ---------------------------------------------------------------------------
#define ATS 68
#define ATT_SMEM_FLOATS (2 * 64 * ATS + 4 * 16 * ATS)
#define ATT_SMEM_BYTES  (ATT_SMEM_FLOATS * 4)

__global__ void __launch_bounds__(128, 3) attn_tc_kernel(
    const float* __restrict__ Qg, const float* __restrict__ Kg,
    const float* __restrict__ Vg, float* __restrict__ Yg)
{
    extern __shared__ float sm[];
    float* bufH = sm;
    float* bufL = sm + 64 * ATS;

    const int qt = (Tt / 64 - 1) - blockIdx.x;   // heavy tiles first
    const int h  = blockIdx.y;
    const int b  = blockIdx.z;
    const int tid  = threadIdx.x;
    const int lane = tid & 31;
    const int w    = tid >> 5;
    const int g  = lane >> 2;
    const int lk = lane & 3;

    float* bufP = sm + 2 * 64 * ATS + w * 16 * ATS;

    // ---- stage Q (scaled) into bufH, then fragment into registers ----
    {
        const float* qsrc = Qg + ((size_t)(b * Tt + qt * 64)) * Cc + h * Dd;
        for (int i = tid; i < 1024; i += 128) {
            int row = i >> 4, c4 = i & 15;
            float4 v = *(const float4*)(qsrc + (size_t)row * Cc + c4 * 4);
            v.x *= 0.125f; v.y *= 0.125f; v.z *= 0.125f; v.w *= 0.125f;
            *(float4*)&bufH[row * ATS + c4 * 4] = v;
        }
    }
    __syncthreads();

    uint32_t qh[8][4], ql[8][4];
    {
        const int r0 = w * 16 + g;
#pragma unroll
        for (int ki = 0; ki < 8; ki++) {
#pragma unroll
            for (int u = 0; u < 4; u++) {
                int rr = r0 + (u & 1) * 8;
                int cc = 8 * ki + lk + (u >> 1) * 4;
                float v = bufH[rr * ATS + cc];
                float hi, lo;
                split_tf32(v, hi, lo);
                qh[ki][u] = __float_as_uint(hi);
                ql[ki][u] = __float_as_uint(lo);
            }
        }
    }

    float4 oacc[8];
#pragma unroll
    for (int ni = 0; ni < 8; ni++) oacc[ni] = make_float4(0.f, 0.f, 0.f, 0.f);
    float m0 = -1e30f, m1 = -1e30f, l0 = 0.f, l1 = 0.f;

    for (int kt = 0; kt <= qt; kt++) {
        __syncthreads();   // bufH/L free (Q frag done / prev V reads done)

        // ---- load K tile, split hi/lo into bufH/bufL ----
        {
            const float* ksrc = Kg + ((size_t)(b * Tt + kt * 64)) * Cc + h * Dd;
            for (int i = tid; i < 1024; i += 128) {
                int row = i >> 4, c4 = i & 15;
                float4 v = *(const float4*)(ksrc + (size_t)row * Cc + c4 * 4);
                float4 hi4, lo4;
                split_tf32(v.x, hi4.x, lo4.x);
                split_tf32(v.y, hi4.y, lo4.y);
                split_tf32(v.z, hi4.z, lo4.z);
                split_tf32(v.w, hi4.w, lo4.w);
                *(float4*)&bufH[row * ATS + c4 * 4] = hi4;
                *(float4*)&bufL[row * ATS + c4 * 4] = lo4;
            }
        }
        __syncthreads();

        // ---- S = Q K^T (3xTF32), 16x64 strip per warp ----
        float4 sacc[8];
#pragma unroll
        for (int ni = 0; ni < 8; ni++) sacc[ni] = make_float4(0.f, 0.f, 0.f, 0.f);

#pragma unroll
        for (int ki = 0; ki < 8; ki++) {
#pragma unroll
            for (int ni = 0; ni < 8; ni++) {
                int br = (ni * 8 + g) * ATS + 8 * ki + lk;
                uint32_t bh0 = __float_as_uint(bufH[br]);
                uint32_t bh1 = __float_as_uint(bufH[br + 4]);
                uint32_t bl0 = __float_as_uint(bufL[br]);
                uint32_t bl1 = __float_as_uint(bufL[br + 4]);
                mma_tf32(sacc[ni], qh[ki][0], qh[ki][1], qh[ki][2], qh[ki][3], bh0, bh1);
                mma_tf32(sacc[ni], ql[ki][0], ql[ki][1], ql[ki][2], ql[ki][3], bh0, bh1);
                mma_tf32(sacc[ni], qh[ki][0], qh[ki][1], qh[ki][2], qh[ki][3], bl0, bl1);
            }
        }

        // ---- causal mask on diagonal tile (local coords) ----
        if (kt == qt) {
            const int rowg = w * 16 + g;
#pragma unroll
            for (int ni = 0; ni < 8; ni++) {
                int c0 = ni * 8 + 2 * lk;
                if (c0 > rowg)     sacc[ni].x = -1e30f;
                if (c0 + 1 > rowg) sacc[ni].y = -1e30f;
                if (c0 > rowg + 8)     sacc[ni].z = -1e30f;
                if (c0 + 1 > rowg + 8) sacc[ni].w = -1e30f;
            }
        }

        // ---- online softmax (rows g / g+8; row spread over 4 lanes) ----
        float mx0 = m0, mx1 = m1;
#pragma unroll
        for (int ni = 0; ni < 8; ni++) {
            mx0 = fmaxf(mx0, fmaxf(sacc[ni].x, sacc[ni].y));
            mx1 = fmaxf(mx1, fmaxf(sacc[ni].z, sacc[ni].w));
        }
        mx0 = fmaxf(mx0, __shfl_xor_sync(0xffffffffu, mx0, 1));
        mx0 = fmaxf(mx0, __shfl_xor_sync(0xffffffffu, mx0, 2));
        mx1 = fmaxf(mx1, __shfl_xor_sync(0xffffffffu, mx1, 1));
        mx1 = fmaxf(mx1, __shfl_xor_sync(0xffffffffu, mx1, 2));

        float a0 = __expf(m0 - mx0);
        float a1 = __expf(m1 - mx1);
        m0 = mx0; m1 = mx1;

        float s0 = 0.f, s1 = 0.f;
#pragma unroll
        for (int ni = 0; ni < 8; ni++) {
            sacc[ni].x = __expf(sacc[ni].x - m0);
            sacc[ni].y = __expf(sacc[ni].y - m0);
            sacc[ni].z = __expf(sacc[ni].z - m1);
            sacc[ni].w = __expf(sacc[ni].w - m1);
            s0 += sacc[ni].x + sacc[ni].y;
            s1 += sacc[ni].z + sacc[ni].w;
        }
        s0 += __shfl_xor_sync(0xffffffffu, s0, 1);
        s0 += __shfl_xor_sync(0xffffffffu, s0, 2);
        s1 += __shfl_xor_sync(0xffffffffu, s1, 1);
        s1 += __shfl_xor_sync(0xffffffffu, s1, 2);
        l0 = l0 * a0 + s0;
        l1 = l1 * a1 + s1;

#pragma unroll
        for (int ni = 0; ni < 8; ni++) {
            oacc[ni].x *= a0; oacc[ni].y *= a0;
            oacc[ni].z *= a1; oacc[ni].w *= a1;
        }

        // ---- stage P (fp32) into the per-warp strip ----
#pragma unroll
        for (int ni = 0; ni < 8; ni++) {
            int cc = ni * 8 + 2 * lk;
            *(float2*)&bufP[g * ATS + cc]       = make_float2(sacc[ni].x, sacc[ni].y);
            *(float2*)&bufP[(g + 8) * ATS + cc] = make_float2(sacc[ni].z, sacc[ni].w);
        }
        __syncwarp();

        __syncthreads();   // all warps done reading K before V overwrites

        // ---- load V transposed [d][token], split hi/lo into bufH/bufL ----
        {
            const int j = tid & 63;
            const int dbase = (tid >> 6) * 32;
            const float* vsrc = Vg + ((size_t)(b * Tt + kt * 64 + j)) * Cc + h * Dd + dbase;
#pragma unroll
            for (int u = 0; u < 8; u++) {
                float4 v = *(const float4*)(vsrc + u * 4);
                float hi, lo;
                int d0 = dbase + u * 4;
                split_tf32(v.x, hi, lo); bufH[(d0 + 0) * ATS + j] = hi; bufL[(d0 + 0) * ATS + j] = lo;
                split_tf32(v.y, hi, lo); bufH[(d0 + 1) * ATS + j] = hi; bufL[(d0 + 1) * ATS + j] = lo;
                split_tf32(v.z, hi, lo); bufH[(d0 + 2) * ATS + j] = hi; bufL[(d0 + 2) * ATS + j] = lo;
                split_tf32(v.w, hi, lo); bufH[(d0 + 3) * ATS + j] = hi; bufL[(d0 + 3) * ATS + j] = lo;
            }
        }
        __syncthreads();

        // ---- O += P V  (3xTF32) ----
#pragma unroll
        for (int ki = 0; ki < 8; ki++) {
            uint32_t ph[4], pl[4];
#pragma unroll
            for (int u = 0; u < 4; u++) {
                int rr = g + (u & 1) * 8;
                int cc = 8 * ki + lk + (u >> 1) * 4;
                float v = bufP[rr * ATS + cc];
                float hi, lo;
                split_tf32(v, hi, lo);
                ph[u] = __float_as_uint(hi);
                pl[u] = __float_as_uint(lo);
            }
#pragma unroll
            for (int ni = 0; ni < 8; ni++) {
                int br = (ni * 8 + g) * ATS + 8 * ki + lk;
                uint32_t bh0 = __float_as_uint(bufH[br]);
                uint32_t bh1 = __float_as_uint(bufH[br + 4]);
                uint32_t bl0 = __float_as_uint(bufL[br]);
                uint32_t bl1 = __float_as_uint(bufL[br + 4]);
                mma_tf32(oacc[ni], ph[0], ph[1], ph[2], ph[3], bh0, bh1);
                mma_tf32(oacc[ni], pl[0], pl[1], pl[2], pl[3], bh0, bh1);
                mma_tf32(oacc[ni], ph[0], ph[1], ph[2], ph[3], bl0, bl1);
            }
        }
    }

    // ---- write normalized output ----
    const float r0inv = 1.f / l0;
    const float r1inv = 1.f / l1;
    const int rowg = qt * 64 + w * 16 + g;
    float* dst = Yg + ((size_t)(b * Tt + rowg)) * Cc + h * Dd;
#pragma unroll
    for (int ni = 0; ni < 8; ni++) {
        int cc = ni * 8 + 2 * lk;
        *(float2*)(dst + cc) = make_float2(oacc[ni].x * r0inv, oacc[ni].y * r0inv);
        *(float2*)(dst + (size_t)8 * Cc + cc) = make_float2(oacc[ni].z * r1inv, oacc[ni].w * r1inv);
    }
}

// ---------------------------------------------------------------------------
// Launch
// ---------------------------------------------------------------------------
extern "C" void kernel_launch(void* const* d_in, const int* in_sizes, int n_in,
                              void* d_out, int out_size)
{
    const float* x  = (const float*)d_in[0];
    const float* Wq = (const float*)d_in[1];
    const float* Wk = (const float*)d_in[2];
    const float* Wv = (const float*)d_in[3];
    const float* Wo = (const float*)d_in[4];
    float* out = (float*)d_out;

    float *qp, *kp, *vp, *yp;
    cudaGetSymbolAddress((void**)&qp, g_Q);
    cudaGetSymbolAddress((void**)&kp, g_K);
    cudaGetSymbolAddress((void**)&vp, g_V);
    cudaGetSymbolAddress((void**)&yp, g_Y);

    cudaFuncSetAttribute(attn_tc_kernel,
                         cudaFuncAttributeMaxDynamicSharedMemorySize,
                         ATT_SMEM_BYTES);

    dim3 ggrid(Cc / 128, Mm / 128);   // (8, 32)
    gemm_tc_kernel<<<ggrid, 256>>>(x, Wq, qp, Mm, Cc, Cc);
    gemm_tc_kernel<<<ggrid, 256>>>(x, Wk, kp, Mm, Cc, Cc);
    gemm_tc_kernel<<<ggrid, 256>>>(x, Wv, vp, Mm, Cc, Cc);

    rope_kernel<<<Bb * Tt, 512>>>(qp, kp);

    dim3 agrid(Tt / 64, Hh, Bb);      // (32, 16, 2)
    attn_tc_kernel<<<agrid, 128, ATT_SMEM_BYTES>>>(qp, kp, vp, yp);

    gemm_tc_kernel<<<ggrid, 256>>>(yp, Wo, out, Mm, Cc, Cc);
}